// round 15
// baseline (speedup 1.0000x reference)
#include <cuda_runtime.h>
#include <cstdint>

#define NPTS 2048
#define BATCH 8
#define KNN 20
#define NEGINF __int_as_float(0xff800000)

typedef unsigned long long u64;

// ---------------- static device scratch (no allocation allowed) ----------------
__device__ float d_S[(size_t)BATCH * NPTS * NPTS];   // 134 MB score matrix
__device__ int   d_idx[BATCH * NPTS * KNN];
__device__ float d_xx[BATCH * NPTS];
__device__ float d_x1[BATCH * NPTS * 64];
__device__ float d_x2[BATCH * NPTS * 64];
__device__ float d_x3[BATCH * NPTS * 128];
__device__ float d_x4[BATCH * NPTS * 256];
// packed edge-conv weights: diff part and center part, u64 = {W[o][2c], W[o][2c+1]}
__device__ u64  d_Wp1d[2 * 64],    d_Wp1c[2 * 64];      // C=3 -> Cp=4
__device__ u64  d_Wp2d[32 * 64],   d_Wp2c[32 * 64];     // C=64
__device__ u64  d_Wp3d[32 * 128],  d_Wp3c[32 * 128];    // C=64
__device__ u64  d_Wp4d[64 * 256],  d_Wp4c[64 * 256];    // C=128
__device__ float d_W5t[512 * 512];
__device__ float d_h5[BATCH * 512];

// ---------------- f32x2 helpers ----------------
__device__ __forceinline__ u64 fma2(u64 a, u64 b, u64 c) {
    u64 d;
    asm("fma.rn.f32x2 %0, %1, %2, %3;" : "=l"(d) : "l"(a), "l"(b), "l"(c));
    return d;
}
__device__ __forceinline__ u64 pack2(float lo, float hi) {
    u64 d;
    asm("mov.b64 %0, {%1, %2};" : "=l"(d) : "f"(lo), "f"(hi));
    return d;
}
__device__ __forceinline__ float2 unpack2(u64 v) {
    float2 r;
    asm("mov.b64 {%0, %1}, %2;" : "=f"(r.x), "=f"(r.y) : "l"(v));
    return r;
}

__device__ __forceinline__ void atomicMaxFloat(float* addr, float v) {
    if (v >= 0.f) atomicMax((int*)addr, __float_as_int(v));
    else          atomicMin((unsigned int*)addr, __float_as_uint(v));
}

// ---------------- one prep kernel: all weight packing + W5 transpose + h5 init ----------------
__device__ __forceinline__ void pack_one(const float* __restrict__ W, u64* __restrict__ Wpd,
                                         u64* __restrict__ Wpc, int O, int C, int i) {
    int c2 = i / O, o = i - c2 * O;
    int c0 = 2 * c2, c1 = 2 * c2 + 1;
    const float* row = W + (size_t)o * 2 * C;
    float a0 = (c0 < C) ? row[c0] : 0.f;
    float a1 = (c1 < C) ? row[c1] : 0.f;
    Wpd[c2 * O + o] = pack2(a0, a1);
    float e0 = (c0 < C) ? row[C + c0] : 0.f;
    float e1 = (c1 < C) ? row[C + c1] : 0.f;
    Wpc[c2 * O + o] = pack2(e0, e1);
}

__global__ void prep_kernel(const float* __restrict__ W1, const float* __restrict__ W2,
                            const float* __restrict__ W3, const float* __restrict__ W4,
                            const float* __restrict__ W5) {
    int tid = blockIdx.x * blockDim.x + threadIdx.x;
    int stride = gridDim.x * blockDim.x;
    for (int i = tid; i < 2 * 64; i += stride)    pack_one(W1, d_Wp1d, d_Wp1c, 64, 3, i);
    for (int i = tid; i < 32 * 64; i += stride)   pack_one(W2, d_Wp2d, d_Wp2c, 64, 64, i);
    for (int i = tid; i < 32 * 128; i += stride)  pack_one(W3, d_Wp3d, d_Wp3c, 128, 64, i);
    for (int i = tid; i < 64 * 256; i += stride)  pack_one(W4, d_Wp4d, d_Wp4c, 256, 128, i);
    for (int i = tid; i < 512 * 512; i += stride) {
        int o = i >> 9, c = i & 511;
        d_W5t[c * 512 + o] = W5[i];
    }
    for (int i = tid; i < BATCH * 512; i += stride) d_h5[i] = NEGINF;
}

// ---------------- squared norms of the raw input (layer 1 only) ----------------
__global__ void norms_kernel(const float* __restrict__ X, int C) {
    int p = blockIdx.x * 4 + (threadIdx.x >> 5);
    int lane = threadIdx.x & 31;
    const float* row = X + (size_t)p * C;
    float s = 0.f;
    for (int c = lane; c < C; c += 32) { float v = row[c]; s += v * v; }
    #pragma unroll
    for (int off = 16; off; off >>= 1) s += __shfl_down_sync(0xffffffffu, s, off);
    if (lane == 0) d_xx[p] = s;
}

// ---------------- neg squared distance: 64x64 tiles, 4x4 microtiles, f32x2 ----------------
template <int C>
__global__ void dist_kernel(const float* __restrict__ X) {
    int b = blockIdx.z;
    int n0 = blockIdx.y * 64, m0 = blockIdx.x * 64;
    __shared__ __align__(16) float An[16][68];
    __shared__ __align__(16) float Am[16][68];
    int tid = threadIdx.x;
    int ty = tid >> 4, tx = tid & 15;     // compute: 4x4 tile at (ty*4, tx*4)
    u64 acc2[4][2];
    #pragma unroll
    for (int i = 0; i < 4; i++) { acc2[i][0] = 0ull; acc2[i][1] = 0ull; }
    const float* Xb = X + (size_t)b * NPTS * C;

    if constexpr (C >= 16) {
        int lrow = tid >> 2;              // 0..63
        int lcq  = (tid & 3) * 4;         // 0,4,8,12
        for (int c0 = 0; c0 < C; c0 += 16) {
            float4 va = *(const float4*)&Xb[(size_t)(n0 + lrow) * C + c0 + lcq];
            float4 vb = *(const float4*)&Xb[(size_t)(m0 + lrow) * C + c0 + lcq];
            An[lcq + 0][lrow] = va.x; An[lcq + 1][lrow] = va.y;
            An[lcq + 2][lrow] = va.z; An[lcq + 3][lrow] = va.w;
            Am[lcq + 0][lrow] = vb.x; Am[lcq + 1][lrow] = vb.y;
            Am[lcq + 2][lrow] = vb.z; Am[lcq + 3][lrow] = vb.w;
            __syncthreads();
            #pragma unroll
            for (int cc = 0; cc < 16; cc++) {
                float4 a4 = *(const float4*)&An[cc][ty * 4];
                ulonglong2 b2 = *(const ulonglong2*)&Am[cc][tx * 4];
                u64 ad;
                ad = pack2(a4.x, a4.x);
                acc2[0][0] = fma2(ad, b2.x, acc2[0][0]);
                acc2[0][1] = fma2(ad, b2.y, acc2[0][1]);
                ad = pack2(a4.y, a4.y);
                acc2[1][0] = fma2(ad, b2.x, acc2[1][0]);
                acc2[1][1] = fma2(ad, b2.y, acc2[1][1]);
                ad = pack2(a4.z, a4.z);
                acc2[2][0] = fma2(ad, b2.x, acc2[2][0]);
                acc2[2][1] = fma2(ad, b2.y, acc2[2][1]);
                ad = pack2(a4.w, a4.w);
                acc2[3][0] = fma2(ad, b2.x, acc2[3][0]);
                acc2[3][1] = fma2(ad, b2.y, acc2[3][1]);
            }
            __syncthreads();
        }
    } else {
        int jj = tid & 15, rr = tid >> 4;
        for (int c0 = 0; c0 < C; c0 += 16) {
            int c = c0 + jj;
            bool cv = (c < C);
            #pragma unroll
            for (int q = 0; q < 4; q++) {
                int r = rr * 4 + q;
                An[jj][r] = cv ? Xb[(size_t)(n0 + r) * C + c] : 0.f;
                Am[jj][r] = cv ? Xb[(size_t)(m0 + r) * C + c] : 0.f;
            }
            __syncthreads();
            #pragma unroll
            for (int cc = 0; cc < 16; cc++) {
                float4 a4 = *(const float4*)&An[cc][ty * 4];
                ulonglong2 b2 = *(const ulonglong2*)&Am[cc][tx * 4];
                u64 ad;
                ad = pack2(a4.x, a4.x);
                acc2[0][0] = fma2(ad, b2.x, acc2[0][0]);
                acc2[0][1] = fma2(ad, b2.y, acc2[0][1]);
                ad = pack2(a4.y, a4.y);
                acc2[1][0] = fma2(ad, b2.x, acc2[1][0]);
                acc2[1][1] = fma2(ad, b2.y, acc2[1][1]);
                ad = pack2(a4.z, a4.z);
                acc2[2][0] = fma2(ad, b2.x, acc2[2][0]);
                acc2[2][1] = fma2(ad, b2.y, acc2[2][1]);
                ad = pack2(a4.w, a4.w);
                acc2[3][0] = fma2(ad, b2.x, acc2[3][0]);
                acc2[3][1] = fma2(ad, b2.y, acc2[3][1]);
            }
            __syncthreads();
        }
    }

    float xm[4];
    #pragma unroll
    for (int j = 0; j < 4; j++) xm[j] = d_xx[b * NPTS + m0 + tx * 4 + j];
    #pragma unroll
    for (int i = 0; i < 4; i++) {
        int n = n0 + ty * 4 + i;
        float xn = d_xx[b * NPTS + n];
        float2 p01 = unpack2(acc2[i][0]);
        float2 p23 = unpack2(acc2[i][1]);
        float4 outv;
        outv.x = 2.f * p01.x - xn - xm[0];
        outv.y = 2.f * p01.y - xn - xm[1];
        outv.z = 2.f * p23.x - xn - xm[2];
        outv.w = 2.f * p23.y - xn - xm[3];
        *(float4*)&d_S[((size_t)b * NPTS + n) * NPTS + m0 + tx * 4] = outv;
    }
}

// ---------------- top-K per row: per-lane top-3 tournament ----------------
__global__ void topk_kernel() {
    __shared__ float buf[4][NPTS];
    int w = threadIdx.x >> 5, lane = threadIdx.x & 31;
    int row = blockIdx.x * 4 + w;                // global row = b*NPTS + n
    const float* S = d_S + (size_t)row * NPTS;
    float* B = buf[w];

    float lv0 = NEGINF, lv1 = NEGINF, lv2 = NEGINF;
    int   li0 = 0x7fffffff, li1 = 0x7fffffff, li2 = 0x7fffffff;

    // build: single pass, stage stripe into (lane-private) smem, keep top-3
    for (int t = 0; t < NPTS / 32; t++) {
        int m = lane + 32 * t;
        float v = S[m];
        B[m] = v;
        if (v > lv2) {                          // strict >: equal keeps earlier (smaller m)
            if (v > lv1) {
                if (v > lv0) { lv2 = lv1; li2 = li1; lv1 = lv0; li1 = li0; lv0 = v; li0 = m; }
                else         { lv2 = lv1; li2 = li1; lv1 = v; li1 = m; }
            } else           { lv2 = v; li2 = m; }
        }
    }

    for (int r = 0; r < KNN; r++) {
        // warp argmax over lane heads: value desc, index asc
        float v = lv0; int mi = li0; int sl = lane;
        #pragma unroll
        for (int off = 16; off; off >>= 1) {
            float ov = __shfl_down_sync(0xffffffffu, v, off);
            int   oi = __shfl_down_sync(0xffffffffu, mi, off);
            int   osl = __shfl_down_sync(0xffffffffu, sl, off);
            if (ov > v || (ov == v && oi < mi)) { v = ov; mi = oi; sl = osl; }
        }
        int wi = __shfl_sync(0xffffffffu, mi, 0);
        int wl = __shfl_sync(0xffffffffu, sl, 0);
        if (lane == 0) d_idx[(size_t)row * KNN + r] = wi;
        if (lane == wl) {
            B[wi] = NEGINF;                     // mark emitted (own stripe)
            lv0 = lv1; li0 = li1;
            lv1 = lv2; li1 = li2;
            lv2 = NEGINF; li2 = 0x7fffffff;
            if (li0 == 0x7fffffff) {            // exhausted: rescan own stripe
                lv0 = lv1 = lv2 = NEGINF;
                li0 = li1 = li2 = 0x7fffffff;
                for (int t = 0; t < NPTS / 32; t++) {
                    int m = lane + 32 * t;
                    float vv = B[m];
                    if (vv > lv2) {
                        if (vv > lv1) {
                            if (vv > lv0) { lv2 = lv1; li2 = li1; lv1 = lv0; li1 = li0; lv0 = vv; li0 = m; }
                            else          { lv2 = lv1; li2 = li1; lv1 = vv; li1 = m; }
                        } else            { lv2 = vv; li2 = m; }
                    }
                }
            }
        }
    }
}

// ---------------- edge conv: PAIRS f32x2 point-pairs per block ----------------
// Diffs for all pairs staged in dynamic smem; per-pair compute loop re-reads the
// weight columns, which L1-hit after pair 0 (4x less L2 weight traffic).
// Per-point arithmetic identical to the 2-point version -> same results.
template <int C, int Cp, int O, int PAIRS, bool WN>
__global__ void edge_kernel(const float* __restrict__ X,
                            const u64* __restrict__ Wpd, const u64* __restrict__ Wpc,
                            const float* __restrict__ g, const float* __restrict__ bias,
                            float* __restrict__ Y) {
    extern __shared__ __align__(16) char smem_raw[];
    u64* xc2   = (u64*)smem_raw;                       // PAIRS*Cp
    u64* diff2 = xc2 + PAIRS * Cp;                     // PAIRS*KNN*Cp
    int* nbr   = (int*)(diff2 + PAIRS * KNN * Cp);     // PAIRS*2*KNN
    float* rbuf = (float*)(nbr + PAIRS * 2 * KNN);     // 2*PAIRS*(O/32)

    int p0 = blockIdx.x * 2 * PAIRS;       // 8 consecutive points, same batch
    int o = threadIdx.x;
    int b = p0 >> 11;

    for (int i = o; i < PAIRS * 2 * KNN; i += O)
        nbr[i] = d_idx[(size_t)(p0 + i / KNN) * KNN + (i % KNN)];
    for (int i = o; i < PAIRS * Cp; i += O) {
        int pr = i / Cp, c = i - pr * Cp;
        float a = (c < C) ? X[(size_t)(p0 + 2 * pr) * C + c] : 0.f;
        float d = (c < C) ? X[(size_t)(p0 + 2 * pr + 1) * C + c] : 0.f;
        xc2[i] = pack2(a, d);
    }
    __syncthreads();
    const float* Xb = X + (size_t)b * NPTS * C;
    for (int e = o; e < PAIRS * KNN * Cp; e += O) {
        int pr = e / (KNN * Cp), r = e - pr * KNN * Cp;
        int k = r / Cp, c = r - k * Cp;
        float v0 = 0.f, v1 = 0.f;
        if (c < C) {
            float2 xc = unpack2(xc2[pr * Cp + c]);
            v0 = Xb[(size_t)nbr[pr * 2 * KNN + k] * C + c] - xc.x;
            v1 = Xb[(size_t)nbr[pr * 2 * KNN + KNN + k] * C + c] - xc.y;
        }
        diff2[e] = pack2(v0, v1);
    }
    __syncthreads();

    float scale = g[o] * rsqrtf(1.f + 1e-5f);
    float bb = bias[o];
    int w = o >> 5, lane = o & 31;
    const int nw = O / 32;

    for (int pr = 0; pr < PAIRS; pr++) {
        const u64* xcp = xc2 + pr * Cp;
        u64 cen2 = 0ull;
        #pragma unroll 4
        for (int c2 = 0; c2 < Cp / 2; c2++) {
            float2 wp = unpack2(Wpc[c2 * O + o]);
            cen2 = fma2(xcp[2 * c2],     pack2(wp.x, wp.x), cen2);
            cen2 = fma2(xcp[2 * c2 + 1], pack2(wp.y, wp.y), cen2);
        }

        u64 acc2[KNN];
        #pragma unroll
        for (int k = 0; k < KNN; k++) acc2[k] = 0ull;

        const u64* dp = diff2 + pr * KNN * Cp;
        for (int c2 = 0; c2 < Cp / 2; c2++) {
            float2 wp = unpack2(Wpd[c2 * O + o]);
            u64 w0 = pack2(wp.x, wp.x);
            u64 w1 = pack2(wp.y, wp.y);
            #pragma unroll
            for (int k = 0; k < KNN; k++) {
                ulonglong2 dv = *(const ulonglong2*)&dp[k * Cp + 2 * c2];
                acc2[k] = fma2(dv.x, w0, acc2[k]);
                acc2[k] = fma2(dv.y, w1, acc2[k]);
            }
        }

        float2 cen = unpack2(cen2);
        float m0 = NEGINF, m1 = NEGINF;
        #pragma unroll
        for (int k = 0; k < KNN; k++) {
            float2 t = unpack2(acc2[k]);
            float h0 = (t.x + cen.x) * scale + bb;
            float h1 = (t.y + cen.y) * scale + bb;
            h0 = (h0 >= 0.f) ? h0 : 0.2f * h0;
            h1 = (h1 >= 0.f) ? h1 : 0.2f * h1;
            m0 = fmaxf(m0, h0);
            m1 = fmaxf(m1, h1);
        }
        Y[(size_t)(p0 + 2 * pr) * O + o] = m0;
        Y[(size_t)(p0 + 2 * pr + 1) * O + o] = m1;

        if (WN) {   // per-warp partial sums of squares, reduced after the pair loop
            float s0 = m0 * m0, s1 = m1 * m1;
            #pragma unroll
            for (int off = 16; off; off >>= 1) {
                s0 += __shfl_down_sync(0xffffffffu, s0, off);
                s1 += __shfl_down_sync(0xffffffffu, s1, off);
            }
            if (lane == 0) { rbuf[(2 * pr) * nw + w] = s0; rbuf[(2 * pr + 1) * nw + w] = s1; }
        }
    }

    if (WN) {
        __syncthreads();
        if (o < 2 * PAIRS) {
            float t = 0.f;
            for (int i = 0; i < nw; i++) t += rbuf[o * nw + i];
            d_xx[p0 + o] = t;
        }
    }
}

// host-side smem size mirror
constexpr int edge_smem(int Cp, int O, int PAIRS) {
    return PAIRS * Cp * 8 + PAIRS * KNN * Cp * 8 + PAIRS * 2 * KNN * 4 + 2 * PAIRS * (O / 32) * 4;
}

// ---------------- concat + W5 + bn/lrelu + max over N (per batch), f32x2 ----------------
__global__ void fuse_kernel(const float* __restrict__ g5, const float* __restrict__ b5) {
    int b = blockIdx.y;
    int n0 = blockIdx.x * 16;
    int t = threadIdx.x;                 // 256 threads
    __shared__ __align__(16) float xc[512][18];   // [channel][point], padded stride
    for (int e = t; e < 16 * 512; e += 256) {
        int pp = e >> 9, c = e & 511;
        int p = b * NPTS + n0 + pp;
        float v;
        if      (c < 64)  v = d_x1[(size_t)p * 64  + c];
        else if (c < 128) v = d_x2[(size_t)p * 64  + (c - 64)];
        else if (c < 256) v = d_x3[(size_t)p * 128 + (c - 128)];
        else              v = d_x4[(size_t)p * 256 + (c - 256)];
        xc[c][pp] = v;
    }
    __syncthreads();

    u64 a0[8], a1[8];
    #pragma unroll
    for (int q = 0; q < 8; q++) { a0[q] = 0ull; a1[q] = 0ull; }
    int o0 = t, o1 = t + 256;
    #pragma unroll 2
    for (int c = 0; c < 512; c++) {
        float w0 = d_W5t[c * 512 + o0];
        float w1 = d_W5t[c * 512 + o1];
        u64 w02 = pack2(w0, w0);
        u64 w12 = pack2(w1, w1);
        #pragma unroll
        for (int q = 0; q < 8; q++) {
            u64 xv = *(const u64*)&xc[c][2 * q];
            a0[q] = fma2(xv, w02, a0[q]);
            a1[q] = fma2(xv, w12, a1[q]);
        }
    }
    float s0 = g5[o0] * rsqrtf(1.f + 1e-5f), s1 = g5[o1] * rsqrtf(1.f + 1e-5f);
    float c0 = b5[o0], c1 = b5[o1];
    float m0 = NEGINF, m1 = NEGINF;
    #pragma unroll
    for (int q = 0; q < 8; q++) {
        float2 v0 = unpack2(a0[q]);
        float2 v1 = unpack2(a1[q]);
        float h;
        h = v0.x * s0 + c0; h = (h >= 0.f) ? h : 0.2f * h; m0 = fmaxf(m0, h);
        h = v0.y * s0 + c0; h = (h >= 0.f) ? h : 0.2f * h; m0 = fmaxf(m0, h);
        h = v1.x * s1 + c1; h = (h >= 0.f) ? h : 0.2f * h; m1 = fmaxf(m1, h);
        h = v1.y * s1 + c1; h = (h >= 0.f) ? h : 0.2f * h; m1 = fmaxf(m1, h);
    }
    atomicMaxFloat(&d_h5[b * 512 + o0], m0);
    atomicMaxFloat(&d_h5[b * 512 + o1], m1);
}

// ---------------- final: feat copy + embedding GEMV ----------------
__global__ void final_kernel(const float* __restrict__ Wemb, float* __restrict__ out) {
    int b = blockIdx.x;
    int t = threadIdx.x;                 // 512 threads
    __shared__ float h[512];
    float v = d_h5[b * 512 + t];
    h[t] = v;
    out[b * 512 + t] = v;                // feat (8,1,512)
    __syncthreads();
    if (t < 256) {
        float s = 0.f;
        #pragma unroll 4
        for (int c = 0; c < 512; c++) s += h[c] * Wemb[t * 512 + c];
        out[BATCH * 512 + b * 256 + t] = s;   // embedding (8,256)
    }
}

// ---------------- launch ----------------
extern "C" void kernel_launch(void* const* d_in, const int* in_sizes, int n_in,
                              void* d_out, int out_size) {
    const float* x    = (const float*)d_in[0];
    const float* W1   = (const float*)d_in[1];
    const float* g1   = (const float*)d_in[2];
    const float* b1   = (const float*)d_in[3];
    const float* W2   = (const float*)d_in[4];
    const float* g2   = (const float*)d_in[5];
    const float* b2   = (const float*)d_in[6];
    const float* W3   = (const float*)d_in[7];
    const float* g3   = (const float*)d_in[8];
    const float* b3   = (const float*)d_in[9];
    const float* W4   = (const float*)d_in[10];
    const float* g4   = (const float*)d_in[11];
    const float* b4   = (const float*)d_in[12];
    const float* W5   = (const float*)d_in[13];
    const float* g5   = (const float*)d_in[14];
    const float* b5   = (const float*)d_in[15];
    const float* Wemb = (const float*)d_in[16];
    float* out = (float*)d_out;

    float *px1, *px2, *px3, *px4;
    u64 *pWp1d, *pWp1c, *pWp2d, *pWp2c, *pWp3d, *pWp3c, *pWp4d, *pWp4c;
    cudaGetSymbolAddress((void**)&px1, d_x1);
    cudaGetSymbolAddress((void**)&px2, d_x2);
    cudaGetSymbolAddress((void**)&px3, d_x3);
    cudaGetSymbolAddress((void**)&px4, d_x4);
    cudaGetSymbolAddress((void**)&pWp1d, d_Wp1d);
    cudaGetSymbolAddress((void**)&pWp1c, d_Wp1c);
    cudaGetSymbolAddress((void**)&pWp2d, d_Wp2d);
    cudaGetSymbolAddress((void**)&pWp2c, d_Wp2c);
    cudaGetSymbolAddress((void**)&pWp3d, d_Wp3d);
    cudaGetSymbolAddress((void**)&pWp3c, d_Wp3c);
    cudaGetSymbolAddress((void**)&pWp4d, d_Wp4d);
    cudaGetSymbolAddress((void**)&pWp4c, d_Wp4c);

    // dynamic smem opt-in (layer 4 exceeds the 48KB default)
    constexpr int S1 = edge_smem(4, 64, 4);
    constexpr int S2 = edge_smem(64, 64, 4);
    constexpr int S3 = edge_smem(64, 128, 4);
    constexpr int S4 = edge_smem(128, 256, 4);
    cudaFuncSetAttribute(edge_kernel<3, 4, 64, 4, true>,
                         cudaFuncAttributeMaxDynamicSharedMemorySize, S1);
    cudaFuncSetAttribute(edge_kernel<64, 64, 64, 4, true>,
                         cudaFuncAttributeMaxDynamicSharedMemorySize, S2);
    cudaFuncSetAttribute(edge_kernel<64, 64, 128, 4, true>,
                         cudaFuncAttributeMaxDynamicSharedMemorySize, S3);
    cudaFuncSetAttribute(edge_kernel<128, 128, 256, 4, false>,
                         cudaFuncAttributeMaxDynamicSharedMemorySize, S4);

    // launch 0: all prep (packs + W5 transpose + h5 init)
    prep_kernel<<<512, 256>>>(W1, W2, W3, W4, W5);

    dim3 dg(NPTS / 64, NPTS / 64, BATCH);
    int nrows = BATCH * NPTS;            // 16384
    int nblk8 = nrows / 8;               // 2048 (8 points per edge block)

    // Layer 1: C=3 -> O=64
    norms_kernel<<<nrows / 4, 128>>>(x, 3);
    dist_kernel<3><<<dg, 256>>>(x);
    topk_kernel<<<nrows / 4, 128>>>();
    edge_kernel<3, 4, 64, 4, true><<<nblk8, 64, S1>>>(x, pWp1d, pWp1c, g1, b1, px1);

    // Layer 2: C=64 -> O=64
    dist_kernel<64><<<dg, 256>>>(px1);
    topk_kernel<<<nrows / 4, 128>>>();
    edge_kernel<64, 64, 64, 4, true><<<nblk8, 64, S2>>>(px1, pWp2d, pWp2c, g2, b2, px2);

    // Layer 3: C=64 -> O=128
    dist_kernel<64><<<dg, 256>>>(px2);
    topk_kernel<<<nrows / 4, 128>>>();
    edge_kernel<64, 64, 128, 4, true><<<nblk8, 128, S3>>>(px2, pWp3d, pWp3c, g3, b3, px3);

    // Layer 4: C=128 -> O=256
    dist_kernel<128><<<dg, 256>>>(px3);
    topk_kernel<<<nrows / 4, 128>>>();
    edge_kernel<128, 128, 256, 4, false><<<nblk8, 256, S4>>>(px3, pWp4d, pWp4c, g4, b4, px4);

    // Final fuse + reductions
    fuse_kernel<<<dim3(NPTS / 16, BATCH), 256>>>(g5, b5);
    final_kernel<<<BATCH, 512>>>(Wemb, out);
}

// round 16
// speedup vs baseline: 1.1128x; 1.1128x over previous
#include <cuda_runtime.h>
#include <cstdint>

#define NPTS 2048
#define BATCH 8
#define KNN 20
#define NEGINF __int_as_float(0xff800000)

typedef unsigned long long u64;

// ---------------- static device scratch (no allocation allowed) ----------------
__device__ float d_S[(size_t)BATCH * NPTS * NPTS];   // 134 MB score matrix
__device__ int   d_idx[BATCH * NPTS * KNN];
__device__ float d_xx[BATCH * NPTS];
__device__ float d_x1[BATCH * NPTS * 64];
__device__ float d_x2[BATCH * NPTS * 64];
__device__ float d_x3[BATCH * NPTS * 128];
__device__ float d_x4[BATCH * NPTS * 256];
// packed edge-conv weights: diff part and center part, u64 = {W[o][2c], W[o][2c+1]}
__device__ u64  d_Wp1d[2 * 64],    d_Wp1c[2 * 64];      // C=3 -> Cp=4
__device__ u64  d_Wp2d[32 * 64],   d_Wp2c[32 * 64];     // C=64
__device__ u64  d_Wp3d[32 * 128],  d_Wp3c[32 * 128];    // C=64
__device__ u64  d_Wp4d[64 * 256],  d_Wp4c[64 * 256];    // C=128
__device__ float d_W5t[512 * 512];
__device__ float d_h5[BATCH * 512];

// ---------------- f32x2 helpers ----------------
__device__ __forceinline__ u64 fma2(u64 a, u64 b, u64 c) {
    u64 d;
    asm("fma.rn.f32x2 %0, %1, %2, %3;" : "=l"(d) : "l"(a), "l"(b), "l"(c));
    return d;
}
__device__ __forceinline__ u64 pack2(float lo, float hi) {
    u64 d;
    asm("mov.b64 %0, {%1, %2};" : "=l"(d) : "f"(lo), "f"(hi));
    return d;
}
__device__ __forceinline__ float2 unpack2(u64 v) {
    float2 r;
    asm("mov.b64 {%0, %1}, %2;" : "=f"(r.x), "=f"(r.y) : "l"(v));
    return r;
}

__device__ __forceinline__ void atomicMaxFloat(float* addr, float v) {
    if (v >= 0.f) atomicMax((int*)addr, __float_as_int(v));
    else          atomicMin((unsigned int*)addr, __float_as_uint(v));
}

// ---------------- one prep kernel: all weight packing + W5 transpose + h5 init ----------------
__device__ __forceinline__ void pack_one(const float* __restrict__ W, u64* __restrict__ Wpd,
                                         u64* __restrict__ Wpc, int O, int C, int i) {
    int c2 = i / O, o = i - c2 * O;
    int c0 = 2 * c2, c1 = 2 * c2 + 1;
    const float* row = W + (size_t)o * 2 * C;
    float a0 = (c0 < C) ? row[c0] : 0.f;
    float a1 = (c1 < C) ? row[c1] : 0.f;
    Wpd[c2 * O + o] = pack2(a0, a1);
    float e0 = (c0 < C) ? row[C + c0] : 0.f;
    float e1 = (c1 < C) ? row[C + c1] : 0.f;
    Wpc[c2 * O + o] = pack2(e0, e1);
}

__global__ void prep_kernel(const float* __restrict__ W1, const float* __restrict__ W2,
                            const float* __restrict__ W3, const float* __restrict__ W4,
                            const float* __restrict__ W5) {
    int tid = blockIdx.x * blockDim.x + threadIdx.x;
    int stride = gridDim.x * blockDim.x;
    for (int i = tid; i < 2 * 64; i += stride)    pack_one(W1, d_Wp1d, d_Wp1c, 64, 3, i);
    for (int i = tid; i < 32 * 64; i += stride)   pack_one(W2, d_Wp2d, d_Wp2c, 64, 64, i);
    for (int i = tid; i < 32 * 128; i += stride)  pack_one(W3, d_Wp3d, d_Wp3c, 128, 64, i);
    for (int i = tid; i < 64 * 256; i += stride)  pack_one(W4, d_Wp4d, d_Wp4c, 256, 128, i);
    for (int i = tid; i < 512 * 512; i += stride) {
        int o = i >> 9, c = i & 511;
        d_W5t[c * 512 + o] = W5[i];
    }
    for (int i = tid; i < BATCH * 512; i += stride) d_h5[i] = NEGINF;
}

// ---------------- squared norms of the raw input (layer 1 only) ----------------
__global__ void norms_kernel(const float* __restrict__ X, int C) {
    int p = blockIdx.x * 4 + (threadIdx.x >> 5);
    int lane = threadIdx.x & 31;
    const float* row = X + (size_t)p * C;
    float s = 0.f;
    for (int c = lane; c < C; c += 32) { float v = row[c]; s += v * v; }
    #pragma unroll
    for (int off = 16; off; off >>= 1) s += __shfl_down_sync(0xffffffffu, s, off);
    if (lane == 0) d_xx[p] = s;
}

// ---------------- neg squared distance: 64x64 tiles, 4x4 microtiles, f32x2 ----------------
template <int C>
__global__ void dist_kernel(const float* __restrict__ X) {
    int b = blockIdx.z;
    int n0 = blockIdx.y * 64, m0 = blockIdx.x * 64;
    __shared__ __align__(16) float An[16][68];
    __shared__ __align__(16) float Am[16][68];
    int tid = threadIdx.x;
    int jj = tid & 15, rr = tid >> 4;     // loader: channel jj, rows rr*4..rr*4+3
    int ty = tid >> 4, tx = tid & 15;     // compute: 4x4 tile at (ty*4, tx*4)
    u64 acc2[4][2];
    #pragma unroll
    for (int i = 0; i < 4; i++) { acc2[i][0] = 0ull; acc2[i][1] = 0ull; }
    const float* Xb = X + (size_t)b * NPTS * C;

    for (int c0 = 0; c0 < C; c0 += 16) {
        int c = c0 + jj;
        bool cv = (c < C);
        #pragma unroll
        for (int q = 0; q < 4; q++) {
            int r = rr * 4 + q;
            An[jj][r] = cv ? Xb[(size_t)(n0 + r) * C + c] : 0.f;
            Am[jj][r] = cv ? Xb[(size_t)(m0 + r) * C + c] : 0.f;
        }
        __syncthreads();
        #pragma unroll
        for (int cc = 0; cc < 16; cc++) {
            float4 a4 = *(const float4*)&An[cc][ty * 4];
            ulonglong2 b2 = *(const ulonglong2*)&Am[cc][tx * 4];
            u64 ad;
            ad = pack2(a4.x, a4.x);
            acc2[0][0] = fma2(ad, b2.x, acc2[0][0]);
            acc2[0][1] = fma2(ad, b2.y, acc2[0][1]);
            ad = pack2(a4.y, a4.y);
            acc2[1][0] = fma2(ad, b2.x, acc2[1][0]);
            acc2[1][1] = fma2(ad, b2.y, acc2[1][1]);
            ad = pack2(a4.z, a4.z);
            acc2[2][0] = fma2(ad, b2.x, acc2[2][0]);
            acc2[2][1] = fma2(ad, b2.y, acc2[2][1]);
            ad = pack2(a4.w, a4.w);
            acc2[3][0] = fma2(ad, b2.x, acc2[3][0]);
            acc2[3][1] = fma2(ad, b2.y, acc2[3][1]);
        }
        __syncthreads();
    }

    float xm[4];
    #pragma unroll
    for (int j = 0; j < 4; j++) xm[j] = d_xx[b * NPTS + m0 + tx * 4 + j];
    #pragma unroll
    for (int i = 0; i < 4; i++) {
        int n = n0 + ty * 4 + i;
        float xn = d_xx[b * NPTS + n];
        float2 p01 = unpack2(acc2[i][0]);
        float2 p23 = unpack2(acc2[i][1]);
        float4 outv;
        outv.x = 2.f * p01.x - xn - xm[0];
        outv.y = 2.f * p01.y - xn - xm[1];
        outv.z = 2.f * p23.x - xn - xm[2];
        outv.w = 2.f * p23.y - xn - xm[3];
        *(float4*)&d_S[((size_t)b * NPTS + n) * NPTS + m0 + tx * 4] = outv;
    }
}

// ---------------- top-K per row v3: smem-free per-lane top-4 tournament ----------------
// Lane owns stripe m = lane + 32t. Build register top-4 straight from gmem; 20 warp
// argmax rounds; a lane that exhausts its 4 rescans its gmem stripe filtered by its
// last emission (bv,bi): un-emitted stripe elements are EXACTLY those with
// (v < bv) || (v == bv && m > bi) under (value desc, index asc) global order.
// Expected rescans/row ~0.005 (P(lane wins >=4 of 20) ~0.5%).
__global__ void topk_kernel() {
    int row = blockIdx.x * 4 + (threadIdx.x >> 5);
    int lane = threadIdx.x & 31;
    const float* S = d_S + (size_t)row * NPTS;

    float lv0 = NEGINF, lv1 = NEGINF, lv2 = NEGINF, lv3 = NEGINF;
    int   li0 = 0x7fffffff, li1 = 0x7fffffff, li2 = 0x7fffffff, li3 = 0x7fffffff;

    #pragma unroll 4
    for (int t = 0; t < NPTS / 32; t++) {
        int m = lane + 32 * t;
        float v = S[m];
        if (v > lv3) {                          // strict >: equal keeps earlier (smaller m)
            if (v > lv1) {
                if (v > lv0) { lv3=lv2; li3=li2; lv2=lv1; li2=li1; lv1=lv0; li1=li0; lv0=v; li0=m; }
                else         { lv3=lv2; li3=li2; lv2=lv1; li2=li1; lv1=v; li1=m; }
            } else {
                if (v > lv2) { lv3=lv2; li3=li2; lv2=v; li2=m; }
                else         { lv3=v; li3=m; }
            }
        }
    }

    for (int r = 0; r < KNN; r++) {
        // warp argmax over lane heads: value desc, index asc
        float v = lv0; int mi = li0; int sl = lane;
        #pragma unroll
        for (int off = 16; off; off >>= 1) {
            float ov = __shfl_down_sync(0xffffffffu, v, off);
            int   oi = __shfl_down_sync(0xffffffffu, mi, off);
            int   osl = __shfl_down_sync(0xffffffffu, sl, off);
            if (ov > v || (ov == v && oi < mi)) { v = ov; mi = oi; sl = osl; }
        }
        int   wi = __shfl_sync(0xffffffffu, mi, 0);
        int   wl = __shfl_sync(0xffffffffu, sl, 0);
        float wv = __shfl_sync(0xffffffffu, v, 0);
        if (lane == 0) d_idx[(size_t)row * KNN + r] = wi;
        if (lane == wl) {
            lv0 = lv1; li0 = li1;
            lv1 = lv2; li1 = li2;
            lv2 = lv3; li2 = li3;
            lv3 = NEGINF; li3 = 0x7fffffff;
            if (li0 == 0x7fffffff) {            // exhausted: filtered rescan from gmem
                float bv = wv; int bi = wi;     // this lane's last emission
                lv0 = lv1 = lv2 = lv3 = NEGINF;
                li0 = li1 = li2 = li3 = 0x7fffffff;
                for (int t = 0; t < NPTS / 32; t++) {
                    int m = lane + 32 * t;
                    float vv = S[m];
                    bool ok = (vv < bv) || (vv == bv && m > bi);
                    if (ok && vv > lv3) {
                        if (vv > lv1) {
                            if (vv > lv0) { lv3=lv2; li3=li2; lv2=lv1; li2=li1; lv1=lv0; li1=li0; lv0=vv; li0=m; }
                            else          { lv3=lv2; li3=li2; lv2=lv1; li2=li1; lv1=vv; li1=m; }
                        } else {
                            if (vv > lv2) { lv3=lv2; li3=li2; lv2=vv; li2=m; }
                            else          { lv3=vv; li3=m; }
                        }
                    }
                }
            }
        }
    }
}

// ---------------- edge conv: 2 POINTS per block packed into f32x2 lanes ----------------
// thread o computes output channel o for both points; weights splat into both lanes.
// WN: also write sum(Y[p][:]^2) to d_xx (feeds the next layer's dist) while Y is in regs.
template <int C, int Cp, int O, bool WN>
__global__ void edge_kernel(const float* __restrict__ X,
                            const u64* __restrict__ Wpd, const u64* __restrict__ Wpc,
                            const float* __restrict__ g, const float* __restrict__ bias,
                            float* __restrict__ Y) {
    int p0 = blockIdx.x * 2;            // global point ids p0, p0+1 (same batch: 2048 even)
    int o = threadIdx.x;
    int b = p0 >> 11;
    __shared__ __align__(16) u64 xc2[Cp];
    __shared__ __align__(16) u64 diff2[KNN * Cp];
    __shared__ int nbr0[KNN], nbr1[KNN];

    if (o < KNN) nbr0[o] = d_idx[(size_t)p0 * KNN + o];
    else if (o < 2 * KNN) nbr1[o - KNN] = d_idx[(size_t)(p0 + 1) * KNN + (o - KNN)];
    for (int c = o; c < Cp; c += O) {
        float a = (c < C) ? X[(size_t)p0 * C + c] : 0.f;
        float d = (c < C) ? X[(size_t)(p0 + 1) * C + c] : 0.f;
        xc2[c] = pack2(a, d);
    }
    __syncthreads();
    const float* Xb = X + (size_t)b * NPTS * C;
    for (int e = o; e < KNN * Cp; e += O) {
        int k = e / Cp, c = e - k * Cp;
        float v0 = 0.f, v1 = 0.f;
        if (c < C) {
            float2 xc = unpack2(xc2[c]);
            v0 = Xb[(size_t)nbr0[k] * C + c] - xc.x;
            v1 = Xb[(size_t)nbr1[k] * C + c] - xc.y;
        }
        diff2[e] = pack2(v0, v1);
    }
    __syncthreads();

    // center term for both points
    u64 cen2 = 0ull;
    #pragma unroll 4
    for (int c2 = 0; c2 < Cp / 2; c2++) {
        float2 wp = unpack2(Wpc[c2 * O + o]);
        cen2 = fma2(xc2[2 * c2],     pack2(wp.x, wp.x), cen2);
        cen2 = fma2(xc2[2 * c2 + 1], pack2(wp.y, wp.y), cen2);
    }

    u64 acc2[KNN];
    #pragma unroll
    for (int k = 0; k < KNN; k++) acc2[k] = 0ull;

    for (int c2 = 0; c2 < Cp / 2; c2++) {
        float2 wp = unpack2(Wpd[c2 * O + o]);
        u64 w0 = pack2(wp.x, wp.x);
        u64 w1 = pack2(wp.y, wp.y);
        #pragma unroll
        for (int k = 0; k < KNN; k++) {
            ulonglong2 dv = *(const ulonglong2*)&diff2[k * Cp + 2 * c2];
            acc2[k] = fma2(dv.x, w0, acc2[k]);
            acc2[k] = fma2(dv.y, w1, acc2[k]);
        }
    }

    float scale = g[o] * rsqrtf(1.f + 1e-5f);
    float bb = bias[o];
    float2 cen = unpack2(cen2);
    float m0 = NEGINF, m1 = NEGINF;
    #pragma unroll
    for (int k = 0; k < KNN; k++) {
        float2 t = unpack2(acc2[k]);
        float h0 = (t.x + cen.x) * scale + bb;
        float h1 = (t.y + cen.y) * scale + bb;
        h0 = (h0 >= 0.f) ? h0 : 0.2f * h0;
        h1 = (h1 >= 0.f) ? h1 : 0.2f * h1;
        m0 = fmaxf(m0, h0);
        m1 = fmaxf(m1, h1);
    }
    Y[(size_t)p0 * O + o] = m0;
    Y[(size_t)(p0 + 1) * O + o] = m1;

    if (WN) {   // block-reduce sum of squares -> next layer's xx
        __shared__ float r0[O / 32], r1[O / 32];
        int w = o >> 5, lane = o & 31;
        float s0 = m0 * m0, s1 = m1 * m1;
        #pragma unroll
        for (int off = 16; off; off >>= 1) {
            s0 += __shfl_down_sync(0xffffffffu, s0, off);
            s1 += __shfl_down_sync(0xffffffffu, s1, off);
        }
        if (lane == 0) { r0[w] = s0; r1[w] = s1; }
        __syncthreads();
        if (o == 0) {
            float t0 = 0.f, t1 = 0.f;
            #pragma unroll
            for (int i = 0; i < O / 32; i++) { t0 += r0[i]; t1 += r1[i]; }
            d_xx[p0] = t0;
            d_xx[p0 + 1] = t1;
        }
    }
}

// ---------------- concat + W5 + bn/lrelu + max over N (per batch), f32x2 ----------------
__global__ void fuse_kernel(const float* __restrict__ g5, const float* __restrict__ b5) {
    int b = blockIdx.y;
    int n0 = blockIdx.x * 16;
    int t = threadIdx.x;                 // 256 threads
    __shared__ __align__(16) float xc[512][18];   // [channel][point], padded stride
    for (int e = t; e < 16 * 512; e += 256) {
        int pp = e >> 9, c = e & 511;
        int p = b * NPTS + n0 + pp;
        float v;
        if      (c < 64)  v = d_x1[(size_t)p * 64  + c];
        else if (c < 128) v = d_x2[(size_t)p * 64  + (c - 64)];
        else if (c < 256) v = d_x3[(size_t)p * 128 + (c - 128)];
        else              v = d_x4[(size_t)p * 256 + (c - 256)];
        xc[c][pp] = v;
    }
    __syncthreads();

    u64 a0[8], a1[8];
    #pragma unroll
    for (int q = 0; q < 8; q++) { a0[q] = 0ull; a1[q] = 0ull; }
    int o0 = t, o1 = t + 256;
    #pragma unroll 2
    for (int c = 0; c < 512; c++) {
        float w0 = d_W5t[c * 512 + o0];
        float w1 = d_W5t[c * 512 + o1];
        u64 w02 = pack2(w0, w0);
        u64 w12 = pack2(w1, w1);
        #pragma unroll
        for (int q = 0; q < 8; q++) {
            u64 xv = *(const u64*)&xc[c][2 * q];
            a0[q] = fma2(xv, w02, a0[q]);
            a1[q] = fma2(xv, w12, a1[q]);
        }
    }
    float s0 = g5[o0] * rsqrtf(1.f + 1e-5f), s1 = g5[o1] * rsqrtf(1.f + 1e-5f);
    float c0 = b5[o0], c1 = b5[o1];
    float m0 = NEGINF, m1 = NEGINF;
    #pragma unroll
    for (int q = 0; q < 8; q++) {
        float2 v0 = unpack2(a0[q]);
        float2 v1 = unpack2(a1[q]);
        float h;
        h = v0.x * s0 + c0; h = (h >= 0.f) ? h : 0.2f * h; m0 = fmaxf(m0, h);
        h = v0.y * s0 + c0; h = (h >= 0.f) ? h : 0.2f * h; m0 = fmaxf(m0, h);
        h = v1.x * s1 + c1; h = (h >= 0.f) ? h : 0.2f * h; m1 = fmaxf(m1, h);
        h = v1.y * s1 + c1; h = (h >= 0.f) ? h : 0.2f * h; m1 = fmaxf(m1, h);
    }
    atomicMaxFloat(&d_h5[b * 512 + o0], m0);
    atomicMaxFloat(&d_h5[b * 512 + o1], m1);
}

// ---------------- final: feat copy + embedding GEMV ----------------
__global__ void final_kernel(const float* __restrict__ Wemb, float* __restrict__ out) {
    int b = blockIdx.x;
    int t = threadIdx.x;                 // 512 threads
    __shared__ float h[512];
    float v = d_h5[b * 512 + t];
    h[t] = v;
    out[b * 512 + t] = v;                // feat (8,1,512)
    __syncthreads();
    if (t < 256) {
        float s = 0.f;
        #pragma unroll 4
        for (int c = 0; c < 512; c++) s += h[c] * Wemb[t * 512 + c];
        out[BATCH * 512 + b * 256 + t] = s;   // embedding (8,256)
    }
}

// ---------------- launch ----------------
extern "C" void kernel_launch(void* const* d_in, const int* in_sizes, int n_in,
                              void* d_out, int out_size) {
    const float* x    = (const float*)d_in[0];
    const float* W1   = (const float*)d_in[1];
    const float* g1   = (const float*)d_in[2];
    const float* b1   = (const float*)d_in[3];
    const float* W2   = (const float*)d_in[4];
    const float* g2   = (const float*)d_in[5];
    const float* b2   = (const float*)d_in[6];
    const float* W3   = (const float*)d_in[7];
    const float* g3   = (const float*)d_in[8];
    const float* b3   = (const float*)d_in[9];
    const float* W4   = (const float*)d_in[10];
    const float* g4   = (const float*)d_in[11];
    const float* b4   = (const float*)d_in[12];
    const float* W5   = (const float*)d_in[13];
    const float* g5   = (const float*)d_in[14];
    const float* b5   = (const float*)d_in[15];
    const float* Wemb = (const float*)d_in[16];
    float* out = (float*)d_out;

    float *px1, *px2, *px3, *px4;
    u64 *pWp1d, *pWp1c, *pWp2d, *pWp2c, *pWp3d, *pWp3c, *pWp4d, *pWp4c;
    cudaGetSymbolAddress((void**)&px1, d_x1);
    cudaGetSymbolAddress((void**)&px2, d_x2);
    cudaGetSymbolAddress((void**)&px3, d_x3);
    cudaGetSymbolAddress((void**)&px4, d_x4);
    cudaGetSymbolAddress((void**)&pWp1d, d_Wp1d);
    cudaGetSymbolAddress((void**)&pWp1c, d_Wp1c);
    cudaGetSymbolAddress((void**)&pWp2d, d_Wp2d);
    cudaGetSymbolAddress((void**)&pWp2c, d_Wp2c);
    cudaGetSymbolAddress((void**)&pWp3d, d_Wp3d);
    cudaGetSymbolAddress((void**)&pWp3c, d_Wp3c);
    cudaGetSymbolAddress((void**)&pWp4d, d_Wp4d);
    cudaGetSymbolAddress((void**)&pWp4c, d_Wp4c);

    // launch 0: all prep (packs + W5 transpose + h5 init)
    prep_kernel<<<512, 256>>>(W1, W2, W3, W4, W5);

    dim3 dg(NPTS / 64, NPTS / 64, BATCH);
    int nrows = BATCH * NPTS;            // 16384
    int nblk2 = nrows / 2;               // 8192 (2 points per edge block)

    // Layer 1: C=3 -> O=64
    norms_kernel<<<nrows / 4, 128>>>(x, 3);
    dist_kernel<3><<<dg, 256>>>(x);
    topk_kernel<<<nrows / 4, 128>>>();
    edge_kernel<3, 4, 64, true><<<nblk2, 64>>>(x, pWp1d, pWp1c, g1, b1, px1);

    // Layer 2: C=64 -> O=64
    dist_kernel<64><<<dg, 256>>>(px1);
    topk_kernel<<<nrows / 4, 128>>>();
    edge_kernel<64, 64, 64, true><<<nblk2, 64>>>(px1, pWp2d, pWp2c, g2, b2, px2);

    // Layer 3: C=64 -> O=128
    dist_kernel<64><<<dg, 256>>>(px2);
    topk_kernel<<<nrows / 4, 128>>>();
    edge_kernel<64, 64, 128, true><<<nblk2, 128>>>(px2, pWp3d, pWp3c, g3, b3, px3);

    // Layer 4: C=128 -> O=256
    dist_kernel<128><<<dg, 256>>>(px3);
    topk_kernel<<<nrows / 4, 128>>>();
    edge_kernel<128, 128, 256, false><<<nblk2, 256>>>(px3, pWp4d, pWp4c, g4, b4, px4);

    // Final fuse + reductions
    fuse_kernel<<<dim3(NPTS / 16, BATCH), 256>>>(g5, b5);
    final_kernel<<<BATCH, 512>>>(Wemb, out);
}

// round 17
// speedup vs baseline: 1.1138x; 1.0008x over previous
#include <cuda_runtime.h>
#include <cstdint>

#define NPTS 2048
#define BATCH 8
#define KNN 20
#define NEGINF __int_as_float(0xff800000)

typedef unsigned long long u64;

// ---------------- static device scratch (no allocation allowed) ----------------
__device__ float d_S[(size_t)BATCH * NPTS * NPTS];   // 134 MB score matrix
__device__ int   d_idx[BATCH * NPTS * KNN];
__device__ float d_xx[BATCH * NPTS];
__device__ float d_x1[BATCH * NPTS * 64];
__device__ float d_x2[BATCH * NPTS * 64];
__device__ float d_x3[BATCH * NPTS * 128];
__device__ float d_x4[BATCH * NPTS * 256];
// packed edge-conv weights: diff part and center part, u64 = {W[o][2c], W[o][2c+1]}
__device__ u64  d_Wp1d[2 * 64],    d_Wp1c[2 * 64];      // C=3 -> Cp=4
__device__ u64  d_Wp2d[32 * 64],   d_Wp2c[32 * 64];     // C=64
__device__ u64  d_Wp3d[32 * 128],  d_Wp3c[32 * 128];    // C=64
__device__ u64  d_Wp4d[64 * 256],  d_Wp4c[64 * 256];    // C=128
__device__ float d_W5t[512 * 512];
__device__ float d_h5[BATCH * 512];

// ---------------- f32x2 helpers ----------------
__device__ __forceinline__ u64 fma2(u64 a, u64 b, u64 c) {
    u64 d;
    asm("fma.rn.f32x2 %0, %1, %2, %3;" : "=l"(d) : "l"(a), "l"(b), "l"(c));
    return d;
}
__device__ __forceinline__ u64 pack2(float lo, float hi) {
    u64 d;
    asm("mov.b64 %0, {%1, %2};" : "=l"(d) : "f"(lo), "f"(hi));
    return d;
}
__device__ __forceinline__ float2 unpack2(u64 v) {
    float2 r;
    asm("mov.b64 {%0, %1}, %2;" : "=f"(r.x), "=f"(r.y) : "l"(v));
    return r;
}

__device__ __forceinline__ void atomicMaxFloat(float* addr, float v) {
    if (v >= 0.f) atomicMax((int*)addr, __float_as_int(v));
    else          atomicMin((unsigned int*)addr, __float_as_uint(v));
}

// ---------------- one prep kernel: all weight packing + W5 transpose + h5 init ----------------
__device__ __forceinline__ void pack_one(const float* __restrict__ W, u64* __restrict__ Wpd,
                                         u64* __restrict__ Wpc, int O, int C, int i) {
    int c2 = i / O, o = i - c2 * O;
    int c0 = 2 * c2, c1 = 2 * c2 + 1;
    const float* row = W + (size_t)o * 2 * C;
    float a0 = (c0 < C) ? row[c0] : 0.f;
    float a1 = (c1 < C) ? row[c1] : 0.f;
    Wpd[c2 * O + o] = pack2(a0, a1);
    float e0 = (c0 < C) ? row[C + c0] : 0.f;
    float e1 = (c1 < C) ? row[C + c1] : 0.f;
    Wpc[c2 * O + o] = pack2(e0, e1);
}

__global__ void prep_kernel(const float* __restrict__ W1, const float* __restrict__ W2,
                            const float* __restrict__ W3, const float* __restrict__ W4,
                            const float* __restrict__ W5) {
    int tid = blockIdx.x * blockDim.x + threadIdx.x;
    int stride = gridDim.x * blockDim.x;
    for (int i = tid; i < 2 * 64; i += stride)    pack_one(W1, d_Wp1d, d_Wp1c, 64, 3, i);
    for (int i = tid; i < 32 * 64; i += stride)   pack_one(W2, d_Wp2d, d_Wp2c, 64, 64, i);
    for (int i = tid; i < 32 * 128; i += stride)  pack_one(W3, d_Wp3d, d_Wp3c, 128, 64, i);
    for (int i = tid; i < 64 * 256; i += stride)  pack_one(W4, d_Wp4d, d_Wp4c, 256, 128, i);
    for (int i = tid; i < 512 * 512; i += stride) {
        int o = i >> 9, c = i & 511;
        d_W5t[c * 512 + o] = W5[i];
    }
    for (int i = tid; i < BATCH * 512; i += stride) d_h5[i] = NEGINF;
}

// ---------------- squared norms of the raw input (layer 1 only) ----------------
__global__ void norms_kernel(const float* __restrict__ X, int C) {
    int p = blockIdx.x * 4 + (threadIdx.x >> 5);
    int lane = threadIdx.x & 31;
    const float* row = X + (size_t)p * C;
    float s = 0.f;
    for (int c = lane; c < C; c += 32) { float v = row[c]; s += v * v; }
    #pragma unroll
    for (int off = 16; off; off >>= 1) s += __shfl_down_sync(0xffffffffu, s, off);
    if (lane == 0) d_xx[p] = s;
}

// ---------------- neg squared distance: 64x64 tiles, 4x4 microtiles, f32x2 ----------------
template <int C>
__global__ void dist_kernel(const float* __restrict__ X) {
    int b = blockIdx.z;
    int n0 = blockIdx.y * 64, m0 = blockIdx.x * 64;
    __shared__ __align__(16) float An[16][68];
    __shared__ __align__(16) float Am[16][68];
    int tid = threadIdx.x;
    int jj = tid & 15, rr = tid >> 4;     // loader: channel jj, rows rr*4..rr*4+3
    int ty = tid >> 4, tx = tid & 15;     // compute: 4x4 tile at (ty*4, tx*4)
    u64 acc2[4][2];
    #pragma unroll
    for (int i = 0; i < 4; i++) { acc2[i][0] = 0ull; acc2[i][1] = 0ull; }
    const float* Xb = X + (size_t)b * NPTS * C;

    for (int c0 = 0; c0 < C; c0 += 16) {
        int c = c0 + jj;
        bool cv = (c < C);
        #pragma unroll
        for (int q = 0; q < 4; q++) {
            int r = rr * 4 + q;
            An[jj][r] = cv ? Xb[(size_t)(n0 + r) * C + c] : 0.f;
            Am[jj][r] = cv ? Xb[(size_t)(m0 + r) * C + c] : 0.f;
        }
        __syncthreads();
        #pragma unroll
        for (int cc = 0; cc < 16; cc++) {
            float4 a4 = *(const float4*)&An[cc][ty * 4];
            ulonglong2 b2 = *(const ulonglong2*)&Am[cc][tx * 4];
            u64 ad;
            ad = pack2(a4.x, a4.x);
            acc2[0][0] = fma2(ad, b2.x, acc2[0][0]);
            acc2[0][1] = fma2(ad, b2.y, acc2[0][1]);
            ad = pack2(a4.y, a4.y);
            acc2[1][0] = fma2(ad, b2.x, acc2[1][0]);
            acc2[1][1] = fma2(ad, b2.y, acc2[1][1]);
            ad = pack2(a4.z, a4.z);
            acc2[2][0] = fma2(ad, b2.x, acc2[2][0]);
            acc2[2][1] = fma2(ad, b2.y, acc2[2][1]);
            ad = pack2(a4.w, a4.w);
            acc2[3][0] = fma2(ad, b2.x, acc2[3][0]);
            acc2[3][1] = fma2(ad, b2.y, acc2[3][1]);
        }
        __syncthreads();
    }

    float xm[4];
    #pragma unroll
    for (int j = 0; j < 4; j++) xm[j] = d_xx[b * NPTS + m0 + tx * 4 + j];
    #pragma unroll
    for (int i = 0; i < 4; i++) {
        int n = n0 + ty * 4 + i;
        float xn = d_xx[b * NPTS + n];
        float2 p01 = unpack2(acc2[i][0]);
        float2 p23 = unpack2(acc2[i][1]);
        float4 outv;
        outv.x = 2.f * p01.x - xn - xm[0];
        outv.y = 2.f * p01.y - xn - xm[1];
        outv.z = 2.f * p23.x - xn - xm[2];
        outv.w = 2.f * p23.y - xn - xm[3];
        *(float4*)&d_S[((size_t)b * NPTS + n) * NPTS + m0 + tx * 4] = outv;
    }
}

// ---------------- top-K per row v4: float4 stripes, smem-free tournament ----------------
// Lane owns m = 128t + 4*lane + j (j=0..3); stripe scanned in increasing m both in
// build and rescan, so strict-> keeps the first (smallest-m) max per lane and the
// warp argmax (value desc, index asc) reproduces jax.lax.top_k set semantics.
__device__ __forceinline__ void top4_insert(float v, int m,
        float& lv0, float& lv1, float& lv2, float& lv3,
        int& li0, int& li1, int& li2, int& li3) {
    if (v > lv3) {
        if (v > lv1) {
            if (v > lv0) { lv3=lv2; li3=li2; lv2=lv1; li2=li1; lv1=lv0; li1=li0; lv0=v; li0=m; }
            else         { lv3=lv2; li3=li2; lv2=lv1; li2=li1; lv1=v; li1=m; }
        } else {
            if (v > lv2) { lv3=lv2; li3=li2; lv2=v; li2=m; }
            else         { lv3=v; li3=m; }
        }
    }
}

__global__ void topk_kernel() {
    int row = blockIdx.x * 4 + (threadIdx.x >> 5);
    int lane = threadIdx.x & 31;
    const float4* S4 = (const float4*)(d_S + (size_t)row * NPTS);

    float lv0 = NEGINF, lv1 = NEGINF, lv2 = NEGINF, lv3 = NEGINF;
    int   li0 = 0x7fffffff, li1 = 0x7fffffff, li2 = 0x7fffffff, li3 = 0x7fffffff;

    #pragma unroll 4
    for (int t = 0; t < NPTS / 128; t++) {
        float4 v4 = S4[t * 32 + lane];
        int m = 128 * t + 4 * lane;
        top4_insert(v4.x, m,     lv0, lv1, lv2, lv3, li0, li1, li2, li3);
        top4_insert(v4.y, m + 1, lv0, lv1, lv2, lv3, li0, li1, li2, li3);
        top4_insert(v4.z, m + 2, lv0, lv1, lv2, lv3, li0, li1, li2, li3);
        top4_insert(v4.w, m + 3, lv0, lv1, lv2, lv3, li0, li1, li2, li3);
    }

    for (int r = 0; r < KNN; r++) {
        // warp argmax over lane heads: value desc, index asc
        float v = lv0; int mi = li0; int sl = lane;
        #pragma unroll
        for (int off = 16; off; off >>= 1) {
            float ov = __shfl_down_sync(0xffffffffu, v, off);
            int   oi = __shfl_down_sync(0xffffffffu, mi, off);
            int   osl = __shfl_down_sync(0xffffffffu, sl, off);
            if (ov > v || (ov == v && oi < mi)) { v = ov; mi = oi; sl = osl; }
        }
        int   wi = __shfl_sync(0xffffffffu, mi, 0);
        int   wl = __shfl_sync(0xffffffffu, sl, 0);
        float wv = __shfl_sync(0xffffffffu, v, 0);
        if (lane == 0) d_idx[(size_t)row * KNN + r] = wi;
        if (lane == wl) {
            lv0 = lv1; li0 = li1;
            lv1 = lv2; li1 = li2;
            lv2 = lv3; li2 = li3;
            lv3 = NEGINF; li3 = 0x7fffffff;
            if (li0 == 0x7fffffff) {            // exhausted: filtered rescan (rare)
                float bv = wv; int bi = wi;     // this lane's last emission
                lv0 = lv1 = lv2 = lv3 = NEGINF;
                li0 = li1 = li2 = li3 = 0x7fffffff;
                for (int t = 0; t < NPTS / 128; t++) {
                    float4 v4 = S4[t * 32 + lane];
                    int m = 128 * t + 4 * lane;
                    float vs[4] = {v4.x, v4.y, v4.z, v4.w};
                    #pragma unroll
                    for (int j = 0; j < 4; j++) {
                        float vv = vs[j];
                        int mm = m + j;
                        bool ok = (vv < bv) || (vv == bv && mm > bi);
                        if (ok) top4_insert(vv, mm, lv0, lv1, lv2, lv3, li0, li1, li2, li3);
                    }
                }
            }
        }
    }
}

// ---------------- edge conv: 2 POINTS per block packed into f32x2 lanes ----------------
// thread o computes output channel o for both points; weights splat into both lanes.
// WN: also write sum(Y[p][:]^2) to d_xx (feeds the next layer's dist) while Y is in regs.
template <int C, int Cp, int O, bool WN>
__global__ void edge_kernel(const float* __restrict__ X,
                            const u64* __restrict__ Wpd, const u64* __restrict__ Wpc,
                            const float* __restrict__ g, const float* __restrict__ bias,
                            float* __restrict__ Y) {
    int p0 = blockIdx.x * 2;            // global point ids p0, p0+1 (same batch: 2048 even)
    int o = threadIdx.x;
    int b = p0 >> 11;
    __shared__ __align__(16) u64 xc2[Cp];
    __shared__ __align__(16) u64 diff2[KNN * Cp];
    __shared__ int nbr0[KNN], nbr1[KNN];

    if (o < KNN) nbr0[o] = d_idx[(size_t)p0 * KNN + o];
    else if (o < 2 * KNN) nbr1[o - KNN] = d_idx[(size_t)(p0 + 1) * KNN + (o - KNN)];
    for (int c = o; c < Cp; c += O) {
        float a = (c < C) ? X[(size_t)p0 * C + c] : 0.f;
        float d = (c < C) ? X[(size_t)(p0 + 1) * C + c] : 0.f;
        xc2[c] = pack2(a, d);
    }
    __syncthreads();
    const float* Xb = X + (size_t)b * NPTS * C;
    for (int e = o; e < KNN * Cp; e += O) {
        int k = e / Cp, c = e - k * Cp;
        float v0 = 0.f, v1 = 0.f;
        if (c < C) {
            float2 xc = unpack2(xc2[c]);
            v0 = Xb[(size_t)nbr0[k] * C + c] - xc.x;
            v1 = Xb[(size_t)nbr1[k] * C + c] - xc.y;
        }
        diff2[e] = pack2(v0, v1);
    }
    __syncthreads();

    // center term for both points
    u64 cen2 = 0ull;
    #pragma unroll 4
    for (int c2 = 0; c2 < Cp / 2; c2++) {
        float2 wp = unpack2(Wpc[c2 * O + o]);
        cen2 = fma2(xc2[2 * c2],     pack2(wp.x, wp.x), cen2);
        cen2 = fma2(xc2[2 * c2 + 1], pack2(wp.y, wp.y), cen2);
    }

    u64 acc2[KNN];
    #pragma unroll
    for (int k = 0; k < KNN; k++) acc2[k] = 0ull;

    for (int c2 = 0; c2 < Cp / 2; c2++) {
        float2 wp = unpack2(Wpd[c2 * O + o]);
        u64 w0 = pack2(wp.x, wp.x);
        u64 w1 = pack2(wp.y, wp.y);
        #pragma unroll
        for (int k = 0; k < KNN; k++) {
            ulonglong2 dv = *(const ulonglong2*)&diff2[k * Cp + 2 * c2];
            acc2[k] = fma2(dv.x, w0, acc2[k]);
            acc2[k] = fma2(dv.y, w1, acc2[k]);
        }
    }

    float scale = g[o] * rsqrtf(1.f + 1e-5f);
    float bb = bias[o];
    float2 cen = unpack2(cen2);
    float m0 = NEGINF, m1 = NEGINF;
    #pragma unroll
    for (int k = 0; k < KNN; k++) {
        float2 t = unpack2(acc2[k]);
        float h0 = (t.x + cen.x) * scale + bb;
        float h1 = (t.y + cen.y) * scale + bb;
        h0 = (h0 >= 0.f) ? h0 : 0.2f * h0;
        h1 = (h1 >= 0.f) ? h1 : 0.2f * h1;
        m0 = fmaxf(m0, h0);
        m1 = fmaxf(m1, h1);
    }
    Y[(size_t)p0 * O + o] = m0;
    Y[(size_t)(p0 + 1) * O + o] = m1;

    if (WN) {   // block-reduce sum of squares -> next layer's xx
        __shared__ float r0[O / 32], r1[O / 32];
        int w = o >> 5, lane = o & 31;
        float s0 = m0 * m0, s1 = m1 * m1;
        #pragma unroll
        for (int off = 16; off; off >>= 1) {
            s0 += __shfl_down_sync(0xffffffffu, s0, off);
            s1 += __shfl_down_sync(0xffffffffu, s1, off);
        }
        if (lane == 0) { r0[w] = s0; r1[w] = s1; }
        __syncthreads();
        if (o == 0) {
            float t0 = 0.f, t1 = 0.f;
            #pragma unroll
            for (int i = 0; i < O / 32; i++) { t0 += r0[i]; t1 += r1[i]; }
            d_xx[p0] = t0;
            d_xx[p0 + 1] = t1;
        }
    }
}

// ---------------- concat + W5 + bn/lrelu + max over N (per batch), f32x2 ----------------
__global__ void fuse_kernel(const float* __restrict__ g5, const float* __restrict__ b5) {
    int b = blockIdx.y;
    int n0 = blockIdx.x * 16;
    int t = threadIdx.x;                 // 256 threads
    __shared__ __align__(16) float xc[512][18];   // [channel][point], padded stride
    for (int e = t; e < 16 * 512; e += 256) {
        int pp = e >> 9, c = e & 511;
        int p = b * NPTS + n0 + pp;
        float v;
        if      (c < 64)  v = d_x1[(size_t)p * 64  + c];
        else if (c < 128) v = d_x2[(size_t)p * 64  + (c - 64)];
        else if (c < 256) v = d_x3[(size_t)p * 128 + (c - 128)];
        else              v = d_x4[(size_t)p * 256 + (c - 256)];
        xc[c][pp] = v;
    }
    __syncthreads();

    u64 a0[8], a1[8];
    #pragma unroll
    for (int q = 0; q < 8; q++) { a0[q] = 0ull; a1[q] = 0ull; }
    int o0 = t, o1 = t + 256;
    #pragma unroll 2
    for (int c = 0; c < 512; c++) {
        float w0 = d_W5t[c * 512 + o0];
        float w1 = d_W5t[c * 512 + o1];
        u64 w02 = pack2(w0, w0);
        u64 w12 = pack2(w1, w1);
        #pragma unroll
        for (int q = 0; q < 8; q++) {
            u64 xv = *(const u64*)&xc[c][2 * q];
            a0[q] = fma2(xv, w02, a0[q]);
            a1[q] = fma2(xv, w12, a1[q]);
        }
    }
    float s0 = g5[o0] * rsqrtf(1.f + 1e-5f), s1 = g5[o1] * rsqrtf(1.f + 1e-5f);
    float c0 = b5[o0], c1 = b5[o1];
    float m0 = NEGINF, m1 = NEGINF;
    #pragma unroll
    for (int q = 0; q < 8; q++) {
        float2 v0 = unpack2(a0[q]);
        float2 v1 = unpack2(a1[q]);
        float h;
        h = v0.x * s0 + c0; h = (h >= 0.f) ? h : 0.2f * h; m0 = fmaxf(m0, h);
        h = v0.y * s0 + c0; h = (h >= 0.f) ? h : 0.2f * h; m0 = fmaxf(m0, h);
        h = v1.x * s1 + c1; h = (h >= 0.f) ? h : 0.2f * h; m1 = fmaxf(m1, h);
        h = v1.y * s1 + c1; h = (h >= 0.f) ? h : 0.2f * h; m1 = fmaxf(m1, h);
    }
    atomicMaxFloat(&d_h5[b * 512 + o0], m0);
    atomicMaxFloat(&d_h5[b * 512 + o1], m1);
}

// ---------------- final: feat copy + embedding GEMV ----------------
__global__ void final_kernel(const float* __restrict__ Wemb, float* __restrict__ out) {
    int b = blockIdx.x;
    int t = threadIdx.x;                 // 512 threads
    __shared__ float h[512];
    float v = d_h5[b * 512 + t];
    h[t] = v;
    out[b * 512 + t] = v;                // feat (8,1,512)
    __syncthreads();
    if (t < 256) {
        float s = 0.f;
        #pragma unroll 4
        for (int c = 0; c < 512; c++) s += h[c] * Wemb[t * 512 + c];
        out[BATCH * 512 + b * 256 + t] = s;   // embedding (8,256)
    }
}

// ---------------- launch ----------------
extern "C" void kernel_launch(void* const* d_in, const int* in_sizes, int n_in,
                              void* d_out, int out_size) {
    const float* x    = (const float*)d_in[0];
    const float* W1   = (const float*)d_in[1];
    const float* g1   = (const float*)d_in[2];
    const float* b1   = (const float*)d_in[3];
    const float* W2   = (const float*)d_in[4];
    const float* g2   = (const float*)d_in[5];
    const float* b2   = (const float*)d_in[6];
    const float* W3   = (const float*)d_in[7];
    const float* g3   = (const float*)d_in[8];
    const float* b3   = (const float*)d_in[9];
    const float* W4   = (const float*)d_in[10];
    const float* g4   = (const float*)d_in[11];
    const float* b4   = (const float*)d_in[12];
    const float* W5   = (const float*)d_in[13];
    const float* g5   = (const float*)d_in[14];
    const float* b5   = (const float*)d_in[15];
    const float* Wemb = (const float*)d_in[16];
    float* out = (float*)d_out;

    float *px1, *px2, *px3, *px4;
    u64 *pWp1d, *pWp1c, *pWp2d, *pWp2c, *pWp3d, *pWp3c, *pWp4d, *pWp4c;
    cudaGetSymbolAddress((void**)&px1, d_x1);
    cudaGetSymbolAddress((void**)&px2, d_x2);
    cudaGetSymbolAddress((void**)&px3, d_x3);
    cudaGetSymbolAddress((void**)&px4, d_x4);
    cudaGetSymbolAddress((void**)&pWp1d, d_Wp1d);
    cudaGetSymbolAddress((void**)&pWp1c, d_Wp1c);
    cudaGetSymbolAddress((void**)&pWp2d, d_Wp2d);
    cudaGetSymbolAddress((void**)&pWp2c, d_Wp2c);
    cudaGetSymbolAddress((void**)&pWp3d, d_Wp3d);
    cudaGetSymbolAddress((void**)&pWp3c, d_Wp3c);
    cudaGetSymbolAddress((void**)&pWp4d, d_Wp4d);
    cudaGetSymbolAddress((void**)&pWp4c, d_Wp4c);

    // launch 0: all prep (packs + W5 transpose + h5 init)
    prep_kernel<<<512, 256>>>(W1, W2, W3, W4, W5);

    dim3 dg(NPTS / 64, NPTS / 64, BATCH);
    int nrows = BATCH * NPTS;            // 16384
    int nblk2 = nrows / 2;               // 8192 (2 points per edge block)

    // Layer 1: C=3 -> O=64
    norms_kernel<<<nrows / 4, 128>>>(x, 3);
    dist_kernel<3><<<dg, 256>>>(x);
    topk_kernel<<<nrows / 4, 128>>>();
    edge_kernel<3, 4, 64, true><<<nblk2, 64>>>(x, pWp1d, pWp1c, g1, b1, px1);

    // Layer 2: C=64 -> O=64
    dist_kernel<64><<<dg, 256>>>(px1);
    topk_kernel<<<nrows / 4, 128>>>();
    edge_kernel<64, 64, 64, true><<<nblk2, 64>>>(px1, pWp2d, pWp2c, g2, b2, px2);

    // Layer 3: C=64 -> O=128
    dist_kernel<64><<<dg, 256>>>(px2);
    topk_kernel<<<nrows / 4, 128>>>();
    edge_kernel<64, 64, 128, true><<<nblk2, 128>>>(px2, pWp3d, pWp3c, g3, b3, px3);

    // Layer 4: C=128 -> O=256
    dist_kernel<128><<<dg, 256>>>(px3);
    topk_kernel<<<nrows / 4, 128>>>();
    edge_kernel<128, 128, 256, false><<<nblk2, 256>>>(px3, pWp4d, pWp4c, g4, b4, px4);

    // Final fuse + reductions
    fuse_kernel<<<dim3(NPTS / 16, BATCH), 256>>>(g5, b5);
    final_kernel<<<BATCH, 512>>>(Wemb, out);
}